// round 13
// baseline (speedup 1.0000x reference)
#include <cuda_runtime.h>
#include <cstdint>
#include <math.h>

// ---------------- device scratch (no allocation allowed) ----------------
__device__ uint32_t g_h1p[128*32*32*4];     // after conv1+bn1, binarized, packed
__device__ uint32_t g_h2p[128*16*16*4];
__device__ uint32_t g_h3p[128*16*16*8];
__device__ uint32_t g_h4p[128*8*8*8];
__device__ uint32_t g_h5p[128*8*8*16];
__device__ float    g_h6 [128*4*4*512];     // fp output after conv6/pool/bn6
__device__ uint32_t g_w2p[9*4*128];
__device__ uint32_t g_w3p[9*4*256];
__device__ uint32_t g_w4p[9*8*256];
__device__ uint32_t g_w5p[9*8*512];
__device__ uint32_t g_w6p[9*16*512];
__device__ int      g_pw2[9*128];           // per-tap weight popcounts (edge corrections)
__device__ int      g_pw3[9*256];
__device__ int      g_pw4[9*256];
__device__ int      g_pw5[9*512];
__device__ int      g_pw6[9*512];

// ---------------- weight bit-packing (device helper) ----------------
// w: HWIO [3,3,CI,CO] floats -> wp[(tap*IW + word)*CO + co], bit b = (w[tap, word*32+b, co] > 0)
__device__ __forceinline__ void pack_dev(const float* __restrict__ w, uint32_t* __restrict__ wp,
                                         int CI, int CO, int idx) {
    int IW = CI / 32;
    int total = 9 * IW * CO;
    if (idx >= total) return;
    int co   = idx % CO;
    int word = (idx / CO) % IW;
    int tap  = idx / (CO * IW);
    uint32_t bits = 0;
    #pragma unroll 8
    for (int b = 0; b < 32; b++) {
        float v = w[(tap * CI + word * 32 + b) * CO + co];   // coalesced across co
        bits |= (v > 0.f ? 1u : 0u) << b;
    }
    wp[(tap * IW + word) * CO + co] = bits;
}

// ---------------- per-tap weight popcount (from float weights, independent of packing) ------
__device__ __forceinline__ void pw_dev(const float* __restrict__ w, int* __restrict__ pwt,
                                       int CI, int CO, int idx) {
    if (idx >= 9 * CO) return;
    int co = idx % CO, t = idx / CO;
    int cnt = 0;
    for (int ci = 0; ci < CI; ci++)
        cnt += (w[(t * CI + ci) * CO + co] > 0.f) ? 1 : 0;   // coalesced across co
    pwt[t * CO + co] = cnt;
}

// ---------------- conv1 (device helper): fp conv 3x3x3->128 + b1 + relu + bn1 + pack ----------
// Numerics bitwise-match the reference: zero-seeded sequential FMA chain over (ky,kx,ci);
// bias added after; relu; bn as separate __fmul_rn then __fadd_rn.
__device__ __forceinline__ void conv1_dev(const float* __restrict__ x, const float* __restrict__ w1,
                                          const float* __restrict__ b1, const float* __restrict__ s1,
                                          const float* __restrict__ t1, int bid, int tid) {
    // bid in [0, 2048): n = bid>>4 (128), yb = bid&15 (16); block handles rows 2yb, 2yb+1
    __shared__ float sx[4][34][3];
    int n = bid >> 4, yb = bid & 15;
    int half = tid >> 7, c = tid & 127;
    int y = 2 * yb + half;

    for (int i = tid; i < 4 * 34 * 3; i += 256) {
        int ci = i % 3;
        int xx = (i / 3) % 34;
        int r  = i / (3 * 34);
        int yy = 2 * yb - 1 + r;
        int xs = xx - 1;
        float v = 0.f;
        if (yy >= 0 && yy < 32 && xs >= 0 && xs < 32)
            v = x[((n * 32 + yy) * 32 + xs) * 3 + ci];
        sx[r][xx][ci] = v;
    }
    __syncthreads();

    float wr[27];
    #pragma unroll
    for (int k = 0; k < 27; k++) wr[k] = w1[k * 128 + c];
    float bb = b1[c], sc = s1[c], tc = t1[c];
    int lane = c & 31, wrp = c >> 5;

    for (int xo = 0; xo < 32; xo++) {
        float acc = 0.f;
        #pragma unroll
        for (int ky = 0; ky < 3; ky++)
            #pragma unroll
            for (int kx = 0; kx < 3; kx++)
                #pragma unroll
                for (int ci = 0; ci < 3; ci++)
                    acc = fmaf(sx[half + ky][xo + kx][ci], wr[(ky * 3 + kx) * 3 + ci], acc);
        float z = __fadd_rn(acc, bb);
        float r = fmaxf(z, 0.f);
        float v = __fadd_rn(__fmul_rn(r, sc), tc);
        unsigned m = __ballot_sync(0xffffffffu, v > 0.f);
        if (lane == 0) g_h1p[((n * 32 + y) * 32 + xo) * 4 + wrp] = m;
    }
}

// ---------------- fused prep: 5 packs + 5 pw tables + conv1 (all mutually independent) -------
// block layout (256 threads each):
//   [0,18)    pack w2   [18,54)   pack w3   [54,126)  pack w4
//   [126,270) pack w5   [270,558) pack w6
//   [558,563) pw w2     [563,572) pw w3     [572,581) pw w4
//   [581,599) pw w5     [599,617) pw w6     [617,2665) conv1
__global__ void __launch_bounds__(256)
prep_kernel(const float* __restrict__ x,  const float* __restrict__ w1,
            const float* __restrict__ b1, const float* __restrict__ s1, const float* __restrict__ t1,
            const float* __restrict__ w2, const float* __restrict__ w3, const float* __restrict__ w4,
            const float* __restrict__ w5, const float* __restrict__ w6) {
    int bid = blockIdx.x, tid = threadIdx.x;
    if      (bid < 18)  pack_dev(w2, g_w2p, 128, 128, bid * 256 + tid);
    else if (bid < 54)  pack_dev(w3, g_w3p, 128, 256, (bid - 18)  * 256 + tid);
    else if (bid < 126) pack_dev(w4, g_w4p, 256, 256, (bid - 54)  * 256 + tid);
    else if (bid < 270) pack_dev(w5, g_w5p, 256, 512, (bid - 126) * 256 + tid);
    else if (bid < 558) pack_dev(w6, g_w6p, 512, 512, (bid - 270) * 256 + tid);
    else if (bid < 563) pw_dev(w2, g_pw2, 128, 128, (bid - 558) * 256 + tid);
    else if (bid < 572) pw_dev(w3, g_pw3, 128, 256, (bid - 563) * 256 + tid);
    else if (bid < 581) pw_dev(w4, g_pw4, 256, 256, (bid - 572) * 256 + tid);
    else if (bid < 599) pw_dev(w5, g_pw5, 256, 512, (bid - 581) * 256 + tid);
    else if (bid < 617) pw_dev(w6, g_pw6, 512, 512, (bid - 599) * 256 + tid);
    else                conv1_dev(x, w1, b1, s1, t1, bid - 617, tid);
}

// ---------------- binary conv v4: 4 conv rows/block, w-pair unroll, LDS.64, IADD3 pairs -----
// in: packed [N, HW, HW, IW]; wp: [9, IW, CO]; pwt: [9, CO]; conv 3x3 SAME, relu,
// optional 2x2 maxpool, bn (mul then add, separate roundings), binarize/pack or fp out.
// grid = ((HW/4)*(HW/NX), N, CO/128); block = 128 threads (one co each).
template<int IW, int CO, int HW, int NX, bool POOL, bool FOUT>
__global__ void __launch_bounds__(128)
bconv4_kernel(const uint32_t* __restrict__ in, const uint32_t* __restrict__ wp,
              const int* __restrict__ pwt,
              const float* __restrict__ scale, const float* __restrict__ bias,
              uint32_t* __restrict__ outb, float* __restrict__ outf) {
    const int XB = HW / NX;
    int bx = blockIdx.x, n = blockIdx.y;
    int co = blockIdx.z * 128 + threadIdx.x;
    int xchunk = bx % XB, yq = bx / XB;
    int r0 = 4 * yq, xb = xchunk * NX;

    __shared__ __align__(16) uint32_t sm[6][NX + 2][IW];
    for (int i = threadIdx.x; i < 6 * (NX + 2) * IW; i += 128) {
        int w  = i % IW;
        int xx = (i / IW) % (NX + 2);
        int rr = i / (IW * (NX + 2));
        int yy = r0 - 1 + rr;
        int xs = xb + xx - 1;
        uint32_t v = 0;
        if (yy >= 0 && yy < HW && xs >= 0 && xs < HW)
            v = in[((n * HW + yy) * HW + xs) * IW + w];
        sm[rr][xx][w] = v;
    }
    __syncthreads();

    int mm[4][NX];
    #pragma unroll
    for (int rr = 0; rr < 4; rr++)
        #pragma unroll
        for (int o = 0; o < NX; o++) mm[rr][o] = 0;

    // hot loop: w pairs; 2 popc + 1 IADD3 per accumulated pair
    #pragma unroll 1
    for (int w2i = 0; w2i < IW / 2; w2i++) {
        uint32_t wt0[9], wt1[9];
        #pragma unroll
        for (int t = 0; t < 9; t++) {
            wt0[t] = wp[(t * IW + 2 * w2i)     * CO + co];   // coalesced across co
            wt1[t] = wp[(t * IW + 2 * w2i + 1) * CO + co];
        }
        #pragma unroll
        for (int iy = 0; iy < 6; iy++) {
            #pragma unroll
            for (int xx = 0; xx < NX + 2; xx++) {
                uint2 av = *reinterpret_cast<const uint2*>(&sm[iy][xx][2 * w2i]); // LDS.64, broadcast
                #pragma unroll
                for (int rr = 0; rr < 4; rr++) {
                    int ky = iy - rr;
                    if (ky < 0 || ky > 2) continue;            // compile-time
                    #pragma unroll
                    for (int kx = 0; kx < 3; kx++) {
                        int o = xx - kx;                        // tile-local output col
                        if (o < 0 || o >= NX) continue;         // compile-time
                        mm[rr][o] += __popc(av.x ^ wt0[ky * 3 + kx])
                                   + __popc(av.y ^ wt1[ky * 3 + kx]);
                    }
                }
            }
        }
    }

    // per-tap weight popcounts (precomputed) for exact SAME-padding corrections
    int pw[9];
    #pragma unroll
    for (int t = 0; t < 9; t++) pw[t] = pwt[t * CO + co];

    float sc = scale[co], tc = bias[co];
    int lane = co & 31, wrp = co >> 5;

    int sums[4][NX];
    #pragma unroll
    for (int rr = 0; rr < 4; rr++) {
        int r = r0 + rr;
        bool top = (r == 0), bot = (r == HW - 1);
        #pragma unroll
        for (int o = 0; o < NX; o++) {
            int gx = xb + o;
            bool left = (gx == 0), right = (gx == HW - 1);
            int corr = 0;
            if (top)  corr += pw[0] + pw[1] + pw[2];
            if (bot)  corr += pw[6] + pw[7] + pw[8];
            if (left) {
                corr += pw[0] + pw[3] + pw[6];
                if (top) corr -= pw[0];
                if (bot) corr -= pw[6];
            }
            if (right) {
                corr += pw[2] + pw[5] + pw[8];
                if (top) corr -= pw[2];
                if (bot) corr -= pw[8];
            }
            int nrow = 3 - (top ? 1 : 0) - (bot ? 1 : 0);
            int ncol = 3 - (left ? 1 : 0) - (right ? 1 : 0);
            sums[rr][o] = nrow * ncol * (32 * IW) - 2 * (mm[rr][o] - corr);
        }
    }

    if (POOL) {
        const int HWo = HW / 2;
        #pragma unroll
        for (int pr = 0; pr < 2; pr++) {
            #pragma unroll
            for (int xo2 = 0; xo2 < NX / 2; xo2++) {
                int p = max(max(sums[2 * pr][2 * xo2],     sums[2 * pr][2 * xo2 + 1]),
                            max(sums[2 * pr + 1][2 * xo2], sums[2 * pr + 1][2 * xo2 + 1]));
                p = max(p, 0);                                     // relu then pool == pool then clamp 0
                float v = __fadd_rn(__fmul_rn((float)p, sc), tc);  // bn: separate roundings
                int yo = 2 * yq + pr;
                int xo = xb / 2 + xo2;
                if (FOUT) {
                    outf[((n * HWo + yo) * HWo + xo) * CO + co] = v;
                } else {
                    unsigned m = __ballot_sync(0xffffffffu, v > 0.f);
                    if (lane == 0)
                        outb[((n * HWo + yo) * HWo + xo) * (CO / 32) + wrp] = m;
                }
            }
        }
    } else {
        #pragma unroll
        for (int rr = 0; rr < 4; rr++) {
            #pragma unroll
            for (int o = 0; o < NX; o++) {
                int s = max(sums[rr][o], 0);
                float v = __fadd_rn(__fmul_rn((float)s, sc), tc);
                unsigned m = __ballot_sync(0xffffffffu, v > 0.f);
                if (lane == 0)
                    outb[((n * HW + r0 + rr) * HW + (xb + o)) * (CO / 32) + wrp] = m;
            }
        }
    }
}

// ---------------- dense (bhwc,cd) + bias + softmax ----------------
__global__ void dense_softmax_kernel(const float* __restrict__ dw, const float* __restrict__ db,
                                     float* __restrict__ out) {
    __shared__ float sw[512 * 10];
    __shared__ float sb[10];
    for (int i = threadIdx.x; i < 512 * 10; i += blockDim.x) sw[i] = dw[i];
    if (threadIdx.x < 10) sb[threadIdx.x] = db[threadIdx.x];
    __syncthreads();

    int warp = threadIdx.x >> 5, lane = threadIdx.x & 31;
    int row = blockIdx.x * (blockDim.x >> 5) + warp;     // 0..2047
    if (row >= 2048) return;

    float acc[10];
    #pragma unroll
    for (int d = 0; d < 10; d++) acc[d] = 0.f;
    const float* h = g_h6 + row * 512;
    for (int c = lane; c < 512; c += 32) {
        float hv = h[c];
        #pragma unroll
        for (int d = 0; d < 10; d++) acc[d] += hv * sw[c * 10 + d];
    }
    #pragma unroll
    for (int d = 0; d < 10; d++) {
        float v = acc[d];
        #pragma unroll
        for (int o = 16; o; o >>= 1) v += __shfl_xor_sync(0xffffffffu, v, o);
        acc[d] = v;
    }
    if (lane == 0) {
        float mx = -1e30f;
        #pragma unroll
        for (int d = 0; d < 10; d++) {
            acc[d] += sb[d];
            mx = fmaxf(mx, acc[d]);
        }
        float se = 0.f;
        #pragma unroll
        for (int d = 0; d < 10; d++) {
            acc[d] = expf(acc[d] - mx);
            se += acc[d];
        }
        float inv = 1.f / se;
        #pragma unroll
        for (int d = 0; d < 10; d++) out[row * 10 + d] = acc[d] * inv;
    }
}

// ---------------- launch ----------------
extern "C" void kernel_launch(void* const* d_in, const int* in_sizes, int n_in,
                              void* d_out, int out_size) {
    const float *x = nullptr, *w1 = nullptr, *b1 = nullptr;
    const float *w2 = nullptr, *w3 = nullptr, *w4 = nullptr, *w5 = nullptr, *w6 = nullptr;
    const float *bns[7] = {0}, *bnb[7] = {0};
    const float *dw = nullptr, *db = nullptr;
    int c128 = 0, c256 = 0, c512 = 0;
    for (int i = 0; i < n_in; i++) {
        const float* p = (const float*)d_in[i];
        switch (in_sizes[i]) {
            case 393216:  x  = p; break;
            case 3456:    w1 = p; break;
            case 147456:  w2 = p; break;
            case 294912:  w3 = p; break;
            case 589824:  w4 = p; break;
            case 1179648: w5 = p; break;
            case 2359296: w6 = p; break;
            case 5120:    dw = p; break;
            case 10:      db = p; break;
            case 128:   // order in both schemes: b1, bn1_s, bn1_b, bn2_s, bn2_b
                if      (c128 == 0) b1     = p;
                else if (c128 == 1) bns[1] = p;
                else if (c128 == 2) bnb[1] = p;
                else if (c128 == 3) bns[2] = p;
                else                bnb[2] = p;
                c128++; break;
            case 256:   // bn3_s, bn3_b, bn4_s, bn4_b
                if      (c256 == 0) bns[3] = p;
                else if (c256 == 1) bnb[3] = p;
                else if (c256 == 2) bns[4] = p;
                else                bnb[4] = p;
                c256++; break;
            case 512:   // bn5_s, bn5_b, bn6_s, bn6_b
                if      (c512 == 0) bns[5] = p;
                else if (c512 == 1) bnb[5] = p;
                else if (c512 == 2) bns[6] = p;
                else                bnb[6] = p;
                c512++; break;
            default: break;
        }
    }

    void *p_h1, *p_h2, *p_h3, *p_h4, *p_h5, *p_h6;
    void *p_w2, *p_w3, *p_w4, *p_w5, *p_w6;
    void *p_pw2, *p_pw3, *p_pw4, *p_pw5, *p_pw6;
    cudaGetSymbolAddress(&p_h1, g_h1p);
    cudaGetSymbolAddress(&p_h2, g_h2p);
    cudaGetSymbolAddress(&p_h3, g_h3p);
    cudaGetSymbolAddress(&p_h4, g_h4p);
    cudaGetSymbolAddress(&p_h5, g_h5p);
    cudaGetSymbolAddress(&p_h6, g_h6);
    cudaGetSymbolAddress(&p_w2, g_w2p);
    cudaGetSymbolAddress(&p_w3, g_w3p);
    cudaGetSymbolAddress(&p_w4, g_w4p);
    cudaGetSymbolAddress(&p_w5, g_w5p);
    cudaGetSymbolAddress(&p_w6, g_w6p);
    cudaGetSymbolAddress(&p_pw2, g_pw2);
    cudaGetSymbolAddress(&p_pw3, g_pw3);
    cudaGetSymbolAddress(&p_pw4, g_pw4);
    cudaGetSymbolAddress(&p_pw5, g_pw5);
    cudaGetSymbolAddress(&p_pw6, g_pw6);

    // fused prep: 5 packs + 5 pw tables + conv1 in one launch (all independent)
    prep_kernel<<<2665, 256>>>(x, w1, b1, bns[1], bnb[1], w2, w3, w4, w5, w6);

    // binary conv stack: grid ((HW/4)*(HW/NX), N, CO/128), block 128
    bconv4_kernel<4, 128, 32, 8, true,  false><<<dim3(8 * 4, 128, 1), 128>>>(
        (const uint32_t*)p_h1, (const uint32_t*)p_w2, (const int*)p_pw2,
        bns[2], bnb[2], (uint32_t*)p_h2, nullptr);
    bconv4_kernel<4, 256, 16, 8, false, false><<<dim3(4 * 2, 128, 2), 128>>>(
        (const uint32_t*)p_h2, (const uint32_t*)p_w3, (const int*)p_pw3,
        bns[3], bnb[3], (uint32_t*)p_h3, nullptr);
    bconv4_kernel<8, 256, 16, 8, true,  false><<<dim3(4 * 2, 128, 2), 128>>>(
        (const uint32_t*)p_h3, (const uint32_t*)p_w4, (const int*)p_pw4,
        bns[4], bnb[4], (uint32_t*)p_h4, nullptr);
    bconv4_kernel<8, 512, 8, 8,  false, false><<<dim3(2 * 1, 128, 4), 128>>>(
        (const uint32_t*)p_h4, (const uint32_t*)p_w5, (const int*)p_pw5,
        bns[5], bnb[5], (uint32_t*)p_h5, nullptr);
    bconv4_kernel<16, 512, 8, 8, true,  true ><<<dim3(2 * 1, 128, 4), 128>>>(
        (const uint32_t*)p_h5, (const uint32_t*)p_w6, (const int*)p_pw6,
        bns[6], bnb[6], nullptr, (float*)p_h6);

    // dense + softmax: 2048 rows, 1 warp per row
    dense_softmax_kernel<<<256, 256>>>(dw, db, (float*)d_out);
}

// round 15
// speedup vs baseline: 1.1910x; 1.1910x over previous
#include <cuda_runtime.h>
#include <cstdint>
#include <math.h>

// ---------------- device scratch (no allocation allowed) ----------------
__device__ uint32_t g_h1p[128*32*32*4];
__device__ uint32_t g_h2p[128*16*16*4];
__device__ uint32_t g_h3p[128*16*16*8];
__device__ uint32_t g_h4p[128*8*8*8];
__device__ __align__(16) char g_h5i[128*8*8*512];    // layer5 out: +/-1 int8, [n][y][x][c]
__device__ float    g_h6 [128*4*4*512];
__device__ uint32_t g_w2p[9*4*128];
__device__ uint32_t g_w3p[9*4*256];
__device__ uint32_t g_w4p[9*8*256];
__device__ uint32_t g_w5p[9*8*512];
__device__ __align__(16) char g_w6i[512*4608];       // B[co][k] +/-1 int8, k = tap*512+ci

// ---------------- int8 tensor-core mma (portable PTX, works under compute_103) ----------
__device__ __forceinline__ void imma16832(int* d, const unsigned* a, const unsigned* b) {
    asm volatile("mma.sync.aligned.m16n8k32.row.col.s32.s8.s8.s32 "
                 "{%0,%1,%2,%3}, {%4,%5,%6,%7}, {%8,%9}, {%0,%1,%2,%3};"
                 : "+r"(d[0]), "+r"(d[1]), "+r"(d[2]), "+r"(d[3])
                 : "r"(a[0]), "r"(a[1]), "r"(a[2]), "r"(a[3]), "r"(b[0]), "r"(b[1]));
}

// ---------------- weight bit-packing (device helper) ----------------
__device__ __forceinline__ void pack_dev(const float* __restrict__ w, uint32_t* __restrict__ wp,
                                         int CI, int CO, int idx) {
    int IW = CI / 32;
    int total = 9 * IW * CO;
    if (idx >= total) return;
    int co   = idx % CO;
    int word = (idx / CO) % IW;
    int tap  = idx / (CO * IW);
    uint32_t bits = 0;
    #pragma unroll 8
    for (int b = 0; b < 32; b++) {
        float v = w[(tap * CI + word * 32 + b) * CO + co];
        bits |= (v > 0.f ? 1u : 0u) << b;
    }
    wp[(tap * IW + word) * CO + co] = bits;
}

// ---------------- w6 [k][co] float -> g_w6i [co][k] int8 +/-1, via smem transpose ------
// 144 tiles: tileco = wq % 8 (64 co), tilek = wq / 8 (256 k)
__device__ __forceinline__ void w6t_dev(const float* __restrict__ w6, int wq, int tid) {
    __shared__ char ts[64][272];
    int cobase = (wq % 8) * 64, kbase = (wq / 8) * 256;
    #pragma unroll 1
    for (int it = 0; it < 64; it++) {
        int col = tid & 63;
        int kl  = (tid >> 6) + 4 * it;
        float v = w6[(kbase + kl) * 512 + cobase + col];   // coalesced over co
        ts[col][kl] = v > 0.f ? (char)1 : (char)-1;
    }
    __syncthreads();
    int row = tid >> 2, q = tid & 3;
    #pragma unroll
    for (int it2 = 0; it2 < 4; it2++) {
        int chunk = q * 4 + it2;                           // 0..15
        uint4 v = *reinterpret_cast<const uint4*>(&ts[row][chunk * 16]);
        *reinterpret_cast<uint4*>(g_w6i + (cobase + row) * 4608 + kbase + chunk * 16) = v;
    }
}

// ---------------- conv1 (device helper) ----------------
__device__ __forceinline__ void conv1_dev(const float* __restrict__ x, const float* __restrict__ w1,
                                          const float* __restrict__ b1, const float* __restrict__ s1,
                                          const float* __restrict__ t1, int bid, int tid) {
    __shared__ float sx[4][34][3];
    int n = bid >> 4, yb = bid & 15;
    int half = tid >> 7, c = tid & 127;
    int y = 2 * yb + half;

    for (int i = tid; i < 4 * 34 * 3; i += 256) {
        int ci = i % 3;
        int xx = (i / 3) % 34;
        int r  = i / (3 * 34);
        int yy = 2 * yb - 1 + r;
        int xs = xx - 1;
        float v = 0.f;
        if (yy >= 0 && yy < 32 && xs >= 0 && xs < 32)
            v = x[((n * 32 + yy) * 32 + xs) * 3 + ci];
        sx[r][xx][ci] = v;
    }
    __syncthreads();

    float wr[27];
    #pragma unroll
    for (int k = 0; k < 27; k++) wr[k] = w1[k * 128 + c];
    float bb = b1[c], sc = s1[c], tc = t1[c];
    int lane = c & 31, wrp = c >> 5;

    for (int xo = 0; xo < 32; xo++) {
        float acc = 0.f;
        #pragma unroll
        for (int ky = 0; ky < 3; ky++)
            #pragma unroll
            for (int kx = 0; kx < 3; kx++)
                #pragma unroll
                for (int ci = 0; ci < 3; ci++)
                    acc = fmaf(sx[half + ky][xo + kx][ci], wr[(ky * 3 + kx) * 3 + ci], acc);
        float z = __fadd_rn(acc, bb);
        float r = fmaxf(z, 0.f);
        float v = __fadd_rn(__fmul_rn(r, sc), tc);
        unsigned m = __ballot_sync(0xffffffffu, v > 0.f);
        if (lane == 0) g_h1p[((n * 32 + y) * 32 + xo) * 4 + wrp] = m;
    }
}

// ---------------- fused prep: packs w2-w5 + w6 transpose + conv1 ----------------
// [0,18) w2  [18,54) w3  [54,126) w4  [126,270) w5  [270,414) w6t  [414,2462) conv1
__global__ void __launch_bounds__(256)
prep_kernel(const float* __restrict__ x,  const float* __restrict__ w1,
            const float* __restrict__ b1, const float* __restrict__ s1, const float* __restrict__ t1,
            const float* __restrict__ w2, const float* __restrict__ w3, const float* __restrict__ w4,
            const float* __restrict__ w5, const float* __restrict__ w6) {
    int bid = blockIdx.x, tid = threadIdx.x;
    if      (bid < 18)  pack_dev(w2, g_w2p, 128, 128, bid * 256 + tid);
    else if (bid < 54)  pack_dev(w3, g_w3p, 128, 256, (bid - 18)  * 256 + tid);
    else if (bid < 126) pack_dev(w4, g_w4p, 256, 256, (bid - 54)  * 256 + tid);
    else if (bid < 270) pack_dev(w5, g_w5p, 256, 512, (bid - 126) * 256 + tid);
    else if (bid < 414) w6t_dev(w6, bid - 270, tid);
    else                conv1_dev(x, w1, b1, s1, t1, bid - 414, tid);
}

// ---------------- binary conv v3 (R12-proven), OUTMODE: 0 = pack bits, 1 = int8 signs ----
template<int IW, int CO, int HW, int NX, bool POOL, int OUTMODE>
__global__ void __launch_bounds__(128)
bconv3_kernel(const uint32_t* __restrict__ in, const uint32_t* __restrict__ wp,
              const float* __restrict__ scale, const float* __restrict__ bias,
              uint32_t* __restrict__ outb, char* __restrict__ outi) {
    const int XB = HW / NX;
    int bx = blockIdx.x, n = blockIdx.y;
    int co = blockIdx.z * 128 + threadIdx.x;
    int xchunk = bx % XB, yb = bx / XB;
    int r0 = 2 * yb, xb = xchunk * NX;

    __shared__ uint32_t sm[4][NX + 2][IW];
    for (int i = threadIdx.x; i < 4 * (NX + 2) * IW; i += 128) {
        int w  = i % IW;
        int xx = (i / IW) % (NX + 2);
        int rr = i / (IW * (NX + 2));
        int yy = r0 - 1 + rr;
        int xs = xb + xx - 1;
        uint32_t v = 0;
        if (yy >= 0 && yy < HW && xs >= 0 && xs < HW)
            v = in[((n * HW + yy) * HW + xs) * IW + w];
        sm[rr][xx][w] = v;
    }
    __syncthreads();

    int mm[2][NX];
    #pragma unroll
    for (int rr = 0; rr < 2; rr++)
        #pragma unroll
        for (int o = 0; o < NX; o++) mm[rr][o] = 0;
    int pw[9];
    #pragma unroll
    for (int t = 0; t < 9; t++) pw[t] = 0;

    #pragma unroll 1
    for (int w = 0; w < IW; w++) {
        uint32_t wt[9];
        #pragma unroll
        for (int t = 0; t < 9; t++) {
            wt[t] = wp[(t * IW + w) * CO + co];
            pw[t] += __popc(wt[t]);
        }
        #pragma unroll
        for (int iy = 0; iy < 4; iy++) {
            #pragma unroll
            for (int xx = 0; xx < NX + 2; xx++) {
                uint32_t a = sm[iy][xx][w];
                #pragma unroll
                for (int rr = 0; rr < 2; rr++) {
                    int ky = iy - rr;
                    if (ky < 0 || ky > 2) continue;
                    #pragma unroll
                    for (int kx = 0; kx < 3; kx++) {
                        int o = xx - kx;
                        if (o < 0 || o >= NX) continue;
                        mm[rr][o] += __popc(a ^ wt[ky * 3 + kx]);
                    }
                }
            }
        }
    }

    float sc = scale[co], tc = bias[co];
    int lane = co & 31, wrp = co >> 5;

    int sums[2][NX];
    #pragma unroll
    for (int rr = 0; rr < 2; rr++) {
        int r = r0 + rr;
        bool top = (r == 0), bot = (r == HW - 1);
        #pragma unroll
        for (int o = 0; o < NX; o++) {
            int gx = xb + o;
            bool left = (gx == 0), right = (gx == HW - 1);
            int corr = 0;
            if (top)  corr += pw[0] + pw[1] + pw[2];
            if (bot)  corr += pw[6] + pw[7] + pw[8];
            if (left) {
                corr += pw[0] + pw[3] + pw[6];
                if (top) corr -= pw[0];
                if (bot) corr -= pw[6];
            }
            if (right) {
                corr += pw[2] + pw[5] + pw[8];
                if (top) corr -= pw[2];
                if (bot) corr -= pw[8];
            }
            int nrow = 3 - (top ? 1 : 0) - (bot ? 1 : 0);
            int ncol = 3 - (left ? 1 : 0) - (right ? 1 : 0);
            sums[rr][o] = nrow * ncol * (32 * IW) - 2 * (mm[rr][o] - corr);
        }
    }

    if (POOL) {
        const int HWo = HW / 2;
        #pragma unroll
        for (int xo2 = 0; xo2 < NX / 2; xo2++) {
            int p = max(max(sums[0][2 * xo2], sums[0][2 * xo2 + 1]),
                        max(sums[1][2 * xo2], sums[1][2 * xo2 + 1]));
            p = max(p, 0);
            float v = __fadd_rn(__fmul_rn((float)p, sc), tc);
            int xo = xb / 2 + xo2;
            unsigned m = __ballot_sync(0xffffffffu, v > 0.f);
            if (lane == 0)
                outb[((n * HWo + yb) * HWo + xo) * (CO / 32) + wrp] = m;
        }
    } else {
        #pragma unroll
        for (int rr = 0; rr < 2; rr++) {
            #pragma unroll
            for (int o = 0; o < NX; o++) {
                int s = max(sums[rr][o], 0);
                float v = __fadd_rn(__fmul_rn((float)s, sc), tc);
                if (OUTMODE == 1) {
                    outi[((n * HW + r0 + rr) * HW + (xb + o)) * CO + co] =
                        v > 0.f ? (char)1 : (char)-1;
                } else {
                    unsigned m = __ballot_sync(0xffffffffu, v > 0.f);
                    if (lane == 0)
                        outb[((n * HW + r0 + rr) * HW + (xb + o)) * (CO / 32) + wrp] = m;
                }
            }
        }
    }
}

// ---------------- layer 6: int8 mma.sync implicit-GEMM + relu + pool + bn -> fp32 -------
// grid (128 imgs, 2 co-halves), block 256 (8 warps).  CTA tile M=64 px, N=256, K=4608.
// Warp tile m32 x n64: wm = wid>>2, wn = wid&3.  K chunks of 64 (tap, cq).
__global__ void __launch_bounds__(256)
conv6_mma_kernel(const float* __restrict__ scale, const float* __restrict__ bias,
                 float* __restrict__ outf) {
    __shared__ unsigned Asm[64 * 20];    // 64 px rows x 64B, 20-word stride (conflict-free)
    __shared__ unsigned Bsm[256 * 20];   // 256 co rows x 64B

    int tid = threadIdx.x, lane = tid & 31, wid = tid >> 5;
    int gid = lane >> 2, tig = lane & 3;
    int wm = wid >> 2, wn = wid & 3;
    int img = blockIdx.x, coBase = blockIdx.y * 256;

    int acc[2][8][4];
    #pragma unroll
    for (int mA = 0; mA < 2; mA++)
        #pragma unroll
        for (int j = 0; j < 8; j++)
            #pragma unroll
            for (int c = 0; c < 4; c++) acc[mA][j][c] = 0;

    const char* h5 = g_h5i + img * (64 * 512);

    #pragma unroll 1
    for (int kk = 0; kk < 72; kk++) {
        int tap = kk >> 3, cq = kk & 7;
        int ky = tap / 3 - 1, kx = tap % 3 - 1;
        if (kk > 0) __syncthreads();
        // stage A: 64 px rows x 64B (im2col, zero pad). 256 uint4, 1 per thread.
        {
            int row = tid >> 2, q = tid & 3;
            int y = row >> 3, x = row & 7;
            int yy = y + ky, xx = x + kx;
            uint4 v = make_uint4(0, 0, 0, 0);
            if ((unsigned)yy < 8u && (unsigned)xx < 8u)
                v = *reinterpret_cast<const uint4*>(h5 + (yy * 8 + xx) * 512 + cq * 64 + q * 16);
            *reinterpret_cast<uint4*>(&Asm[row * 20 + q * 4]) = v;
        }
        // stage B: 256 co rows x 64B. 1024 uint4, 4 per thread.
        #pragma unroll
        for (int it = 0; it < 4; it++) {
            int i = tid + 256 * it;
            int row = i >> 2, q = i & 3;
            uint4 v = *reinterpret_cast<const uint4*>(
                g_w6i + (coBase + row) * 4608 + tap * 512 + cq * 64 + q * 16);
            *reinterpret_cast<uint4*>(&Bsm[row * 20 + q * 4]) = v;
        }
        __syncthreads();

        #pragma unroll
        for (int kc = 0; kc < 2; kc++) {
            unsigned af[2][4];
            #pragma unroll
            for (int mA = 0; mA < 2; mA++) {
                int abase = (wm * 32 + mA * 16 + gid) * 20 + kc * 8 + tig;
                af[mA][0] = Asm[abase];
                af[mA][1] = Asm[abase + 8 * 20];
                af[mA][2] = Asm[abase + 4];
                af[mA][3] = Asm[abase + 8 * 20 + 4];
            }
            #pragma unroll
            for (int j = 0; j < 8; j++) {
                unsigned bf[2];
                int bbase = (wn * 64 + j * 8 + gid) * 20 + kc * 8 + tig;
                bf[0] = Bsm[bbase];
                bf[1] = Bsm[bbase + 4];
                #pragma unroll
                for (int mA = 0; mA < 2; mA++)
                    imma16832(acc[mA][j], af[mA], bf);
            }
        }
    }

    // epilogue: relu + 2x2 maxpool + bn -> fp32
    bool valid = ((lane & 4) == 0);                       // gid even => x even
    #pragma unroll
    for (int mA = 0; mA < 2; mA++) {
        int yo = 2 * wm + mA;                              // pooled y
        int xo = gid >> 1;                                 // pooled x (valid lanes)
        float* orow = outf + ((img * 4 + yo) * 4 + xo) * 512 + coBase;
        #pragma unroll
        for (int j = 0; j < 8; j++) {
            int m0 = max(max(acc[mA][j][0], acc[mA][j][2]), 0);   // y-pool + relu, col 2tig
            int m1 = max(max(acc[mA][j][1], acc[mA][j][3]), 0);   // col 2tig+1
            int p0 = max(m0, __shfl_xor_sync(0xffffffffu, m0, 4)); // x-pool
            int p1 = max(m1, __shfl_xor_sync(0xffffffffu, m1, 4));
            if (valid) {
                int c0 = wn * 64 + j * 8 + 2 * tig;
                float v0 = __fadd_rn(__fmul_rn((float)p0, scale[coBase + c0]), bias[coBase + c0]);
                float v1 = __fadd_rn(__fmul_rn((float)p1, scale[coBase + c0 + 1]), bias[coBase + c0 + 1]);
                orow[c0]     = v0;
                orow[c0 + 1] = v1;
            }
        }
    }
}

// ---------------- dense (bhwc,cd) + bias + softmax ----------------
__global__ void dense_softmax_kernel(const float* __restrict__ dw, const float* __restrict__ db,
                                     float* __restrict__ out) {
    __shared__ float sw[512 * 10];
    __shared__ float sb[10];
    for (int i = threadIdx.x; i < 512 * 10; i += blockDim.x) sw[i] = dw[i];
    if (threadIdx.x < 10) sb[threadIdx.x] = db[threadIdx.x];
    __syncthreads();

    int warp = threadIdx.x >> 5, lane = threadIdx.x & 31;
    int row = blockIdx.x * (blockDim.x >> 5) + warp;
    if (row >= 2048) return;

    float acc[10];
    #pragma unroll
    for (int d = 0; d < 10; d++) acc[d] = 0.f;
    const float* h = g_h6 + row * 512;
    for (int c = lane; c < 512; c += 32) {
        float hv = h[c];
        #pragma unroll
        for (int d = 0; d < 10; d++) acc[d] += hv * sw[c * 10 + d];
    }
    #pragma unroll
    for (int d = 0; d < 10; d++) {
        float v = acc[d];
        #pragma unroll
        for (int o = 16; o; o >>= 1) v += __shfl_xor_sync(0xffffffffu, v, o);
        acc[d] = v;
    }
    if (lane == 0) {
        float mx = -1e30f;
        #pragma unroll
        for (int d = 0; d < 10; d++) { acc[d] += sb[d]; mx = fmaxf(mx, acc[d]); }
        float se = 0.f;
        #pragma unroll
        for (int d = 0; d < 10; d++) { acc[d] = expf(acc[d] - mx); se += acc[d]; }
        float inv = 1.f / se;
        #pragma unroll
        for (int d = 0; d < 10; d++) out[row * 10 + d] = acc[d] * inv;
    }
}

// ---------------- launch ----------------
extern "C" void kernel_launch(void* const* d_in, const int* in_sizes, int n_in,
                              void* d_out, int out_size) {
    const float *x = nullptr, *w1 = nullptr, *b1 = nullptr;
    const float *w2 = nullptr, *w3 = nullptr, *w4 = nullptr, *w5 = nullptr, *w6 = nullptr;
    const float *bns[7] = {0}, *bnb[7] = {0};
    const float *dw = nullptr, *db = nullptr;
    int c128 = 0, c256 = 0, c512 = 0;
    for (int i = 0; i < n_in; i++) {
        const float* p = (const float*)d_in[i];
        switch (in_sizes[i]) {
            case 393216:  x  = p; break;
            case 3456:    w1 = p; break;
            case 147456:  w2 = p; break;
            case 294912:  w3 = p; break;
            case 589824:  w4 = p; break;
            case 1179648: w5 = p; break;
            case 2359296: w6 = p; break;
            case 5120:    dw = p; break;
            case 10:      db = p; break;
            case 128:
                if      (c128 == 0) b1     = p;
                else if (c128 == 1) bns[1] = p;
                else if (c128 == 2) bnb[1] = p;
                else if (c128 == 3) bns[2] = p;
                else                bnb[2] = p;
                c128++; break;
            case 256:
                if      (c256 == 0) bns[3] = p;
                else if (c256 == 1) bnb[3] = p;
                else if (c256 == 2) bns[4] = p;
                else                bnb[4] = p;
                c256++; break;
            case 512:
                if      (c512 == 0) bns[5] = p;
                else if (c512 == 1) bnb[5] = p;
                else if (c512 == 2) bns[6] = p;
                else                bnb[6] = p;
                c512++; break;
            default: break;
        }
    }

    void *p_h1, *p_h2, *p_h3, *p_h4, *p_h5i, *p_h6;
    void *p_w2, *p_w3, *p_w4, *p_w5;
    cudaGetSymbolAddress(&p_h1, g_h1p);
    cudaGetSymbolAddress(&p_h2, g_h2p);
    cudaGetSymbolAddress(&p_h3, g_h3p);
    cudaGetSymbolAddress(&p_h4, g_h4p);
    cudaGetSymbolAddress(&p_h5i, g_h5i);
    cudaGetSymbolAddress(&p_h6, g_h6);
    cudaGetSymbolAddress(&p_w2, g_w2p);
    cudaGetSymbolAddress(&p_w3, g_w3p);
    cudaGetSymbolAddress(&p_w4, g_w4p);
    cudaGetSymbolAddress(&p_w5, g_w5p);

    // prep: packs + w6 int8 transpose + conv1
    prep_kernel<<<2462, 256>>>(x, w1, b1, bns[1], bnb[1], w2, w3, w4, w5, w6);

    // binary conv stack (layers 2-5, popcount; R12-proven config)
    bconv3_kernel<4, 128, 32, 8, true,  0><<<dim3(16 * 4, 128, 1), 128>>>(
        (const uint32_t*)p_h1, (const uint32_t*)p_w2, bns[2], bnb[2], (uint32_t*)p_h2, nullptr);
    bconv3_kernel<4, 256, 16, 8, false, 0><<<dim3(8 * 2, 128, 2), 128>>>(
        (const uint32_t*)p_h2, (const uint32_t*)p_w3, bns[3], bnb[3], (uint32_t*)p_h3, nullptr);
    bconv3_kernel<8, 256, 16, 8, true,  0><<<dim3(8 * 2, 128, 2), 128>>>(
        (const uint32_t*)p_h3, (const uint32_t*)p_w4, bns[4], bnb[4], (uint32_t*)p_h4, nullptr);
    bconv3_kernel<8, 512, 8, 8,  false, 1><<<dim3(4 * 1, 128, 4), 128>>>(
        (const uint32_t*)p_h4, (const uint32_t*)p_w5, bns[5], bnb[5],
        nullptr, (char*)p_h5i);

    // layer 6: int8 tensor-core implicit GEMM
    conv6_mma_kernel<<<dim3(128, 2), 256>>>(bns[6], bnb[6], (float*)p_h6);

    // dense + softmax
    dense_softmax_kernel<<<256, 256>>>(dw, db, (float*)d_out);
}

// round 16
// speedup vs baseline: 2.1264x; 1.7854x over previous
#include <cuda_runtime.h>
#include <cstdint>
#include <math.h>

// ---------------- device scratch (no allocation allowed) ----------------
__device__ uint32_t g_h1p[128*32*32*4];
__device__ uint32_t g_h2p[128*16*16*4];
__device__ uint32_t g_h3p[128*16*16*8];
__device__ uint32_t g_h4p[128*8*8*8];
__device__ uint32_t g_h5p[128*8*8*16];
__device__ float    g_h6 [128*4*4*512];
__device__ uint32_t g_w2p[9*4*128];
__device__ uint32_t g_w3p[9*4*256];
__device__ uint32_t g_w4p[9*8*256];
__device__ uint32_t g_w5p[9*8*512];
__device__ uint32_t g_w6p[9*16*512];
__device__ int      g_pw2[9*128];           // per-tap weight popcounts (edge corrections)
__device__ int      g_pw3[9*256];
__device__ int      g_pw4[9*256];
__device__ int      g_pw5[9*512];
__device__ int      g_pw6[9*512];

// ---------------- single-LOP3 parity / majority (guaranteed one SASS op) ----------------
template<int IMM>
__device__ __forceinline__ uint32_t lop3i(uint32_t a, uint32_t b, uint32_t c) {
    uint32_t r;
    asm("lop3.b32 %0, %1, %2, %3, %4;" : "=r"(r) : "r"(a), "r"(b), "r"(c), "n"(IMM));
    return r;
}
// Carry-save add of 4 bit-vectors into (ones, twos) state + popc of the 4s-carries.
__device__ __forceinline__ void csa4(uint32_t& ones, uint32_t& twos, int& cnt4,
                                     uint32_t x1, uint32_t x2, uint32_t x3, uint32_t x4) {
    uint32_t s1 = lop3i<0x96>(ones, x1, x2);   // parity
    uint32_t c1 = lop3i<0xE8>(ones, x1, x2);   // majority
    uint32_t s2 = lop3i<0x96>(s1, x3, x4);
    uint32_t c2 = lop3i<0xE8>(s1, x3, x4);
    uint32_t s3 = lop3i<0x96>(twos, c1, c2);
    uint32_t c3 = lop3i<0xE8>(twos, c1, c2);
    ones = s2; twos = s3;
    cnt4 += __popc(c3);
}

// ---------------- weight bit-packing (device helper) ----------------
__device__ __forceinline__ void pack_dev(const float* __restrict__ w, uint32_t* __restrict__ wp,
                                         int CI, int CO, int idx) {
    int IW = CI / 32;
    int total = 9 * IW * CO;
    if (idx >= total) return;
    int co   = idx % CO;
    int word = (idx / CO) % IW;
    int tap  = idx / (CO * IW);
    uint32_t bits = 0;
    #pragma unroll 8
    for (int b = 0; b < 32; b++) {
        float v = w[(tap * CI + word * 32 + b) * CO + co];
        bits |= (v > 0.f ? 1u : 0u) << b;
    }
    wp[(tap * IW + word) * CO + co] = bits;
}

// ---------------- per-tap weight popcount tables ----------------
__device__ __forceinline__ void pw_dev(const float* __restrict__ w, int* __restrict__ pwt,
                                       int CI, int CO, int idx) {
    if (idx >= 9 * CO) return;
    int co = idx % CO, t = idx / CO;
    int cnt = 0;
    for (int ci = 0; ci < CI; ci++)
        cnt += (w[(t * CI + ci) * CO + co] > 0.f) ? 1 : 0;
    pwt[t * CO + co] = cnt;
}

// ---------------- conv1 (device helper) ----------------
__device__ __forceinline__ void conv1_dev(const float* __restrict__ x, const float* __restrict__ w1,
                                          const float* __restrict__ b1, const float* __restrict__ s1,
                                          const float* __restrict__ t1, int bid, int tid) {
    __shared__ float sx[4][34][3];
    int n = bid >> 4, yb = bid & 15;
    int half = tid >> 7, c = tid & 127;
    int y = 2 * yb + half;

    for (int i = tid; i < 4 * 34 * 3; i += 256) {
        int ci = i % 3;
        int xx = (i / 3) % 34;
        int r  = i / (3 * 34);
        int yy = 2 * yb - 1 + r;
        int xs = xx - 1;
        float v = 0.f;
        if (yy >= 0 && yy < 32 && xs >= 0 && xs < 32)
            v = x[((n * 32 + yy) * 32 + xs) * 3 + ci];
        sx[r][xx][ci] = v;
    }
    __syncthreads();

    float wr[27];
    #pragma unroll
    for (int k = 0; k < 27; k++) wr[k] = w1[k * 128 + c];
    float bb = b1[c], sc = s1[c], tc = t1[c];
    int lane = c & 31, wrp = c >> 5;

    for (int xo = 0; xo < 32; xo++) {
        float acc = 0.f;
        #pragma unroll
        for (int ky = 0; ky < 3; ky++)
            #pragma unroll
            for (int kx = 0; kx < 3; kx++)
                #pragma unroll
                for (int ci = 0; ci < 3; ci++)
                    acc = fmaf(sx[half + ky][xo + kx][ci], wr[(ky * 3 + kx) * 3 + ci], acc);
        float z = __fadd_rn(acc, bb);
        float r = fmaxf(z, 0.f);
        float v = __fadd_rn(__fmul_rn(r, sc), tc);
        unsigned m = __ballot_sync(0xffffffffu, v > 0.f);
        if (lane == 0) g_h1p[((n * 32 + y) * 32 + xo) * 4 + wrp] = m;
    }
}

// ---------------- fused prep: 5 packs + 5 pw tables + conv1 ----------------
// [0,18) w2  [18,54) w3  [54,126) w4  [126,270) w5  [270,558) w6
// [558,563) pw2 [563,572) pw3 [572,581) pw4 [581,599) pw5 [599,617) pw6 [617,2665) conv1
__global__ void __launch_bounds__(256)
prep_kernel(const float* __restrict__ x,  const float* __restrict__ w1,
            const float* __restrict__ b1, const float* __restrict__ s1, const float* __restrict__ t1,
            const float* __restrict__ w2, const float* __restrict__ w3, const float* __restrict__ w4,
            const float* __restrict__ w5, const float* __restrict__ w6) {
    int bid = blockIdx.x, tid = threadIdx.x;
    if      (bid < 18)  pack_dev(w2, g_w2p, 128, 128, bid * 256 + tid);
    else if (bid < 54)  pack_dev(w3, g_w3p, 128, 256, (bid - 18)  * 256 + tid);
    else if (bid < 126) pack_dev(w4, g_w4p, 256, 256, (bid - 54)  * 256 + tid);
    else if (bid < 270) pack_dev(w5, g_w5p, 256, 512, (bid - 126) * 256 + tid);
    else if (bid < 558) pack_dev(w6, g_w6p, 512, 512, (bid - 270) * 256 + tid);
    else if (bid < 563) pw_dev(w2, g_pw2, 128, 128, (bid - 558) * 256 + tid);
    else if (bid < 572) pw_dev(w3, g_pw3, 128, 256, (bid - 563) * 256 + tid);
    else if (bid < 581) pw_dev(w4, g_pw4, 256, 256, (bid - 572) * 256 + tid);
    else if (bid < 599) pw_dev(w5, g_pw5, 256, 512, (bid - 581) * 256 + tid);
    else if (bid < 617) pw_dev(w6, g_pw6, 512, 512, (bid - 599) * 256 + tid);
    else                conv1_dev(x, w1, b1, s1, t1, bid - 617, tid);
}

// ---------------- binary conv v6: CSA bit-counting + popc/CSA pipe split ----------------
// in: packed [N, HW, HW, IW]; wp: [9, IW, CO]; pwt: [9, CO].
// Taps 0-2 (ky=0): direct popc path. Taps 3-8: Harley-Seal CSA (1 popc / 4 words).
// grid = ((HW/2)*(HW/NX), N, CO/128), block 128.
template<int IW, int CO, int HW, int NX, bool POOL, bool FOUT>
__global__ void __launch_bounds__(128)
bconv6_kernel(const uint32_t* __restrict__ in, const uint32_t* __restrict__ wp,
              const int* __restrict__ pwt,
              const float* __restrict__ scale, const float* __restrict__ bias,
              uint32_t* __restrict__ outb, float* __restrict__ outf) {
    const int XB = HW / NX;
    const int QW = IW / 4;
    int bx = blockIdx.x, n = blockIdx.y;
    int co = blockIdx.z * 128 + threadIdx.x;
    int xchunk = bx % XB, yb = bx / XB;
    int r0 = 2 * yb, xb = xchunk * NX;

    __shared__ __align__(16) uint32_t sm[4][NX + 2][IW];
    for (int i = threadIdx.x; i < 4 * (NX + 2) * IW; i += 128) {
        int w  = i % IW;
        int xx = (i / IW) % (NX + 2);
        int rr = i / (IW * (NX + 2));
        int yy = r0 - 1 + rr;
        int xs = xb + xx - 1;
        uint32_t v = 0;
        if (yy >= 0 && yy < HW && xs >= 0 && xs < HW)
            v = in[((n * HW + yy) * HW + xs) * IW + w];
        sm[rr][xx][w] = v;
    }
    __syncthreads();

    int      dirm[2][NX];
    uint32_t ones[2][NX], twos[2][NX];
    int      cnt4[2][NX];
    #pragma unroll
    for (int rr = 0; rr < 2; rr++)
        #pragma unroll
        for (int o = 0; o < NX; o++) {
            dirm[rr][o] = 0; ones[rr][o] = 0u; twos[rr][o] = 0u; cnt4[rr][o] = 0;
        }

    #pragma unroll 1
    for (int q = 0; q < QW; q++) {
        uint32_t wq[9][4];
        #pragma unroll
        for (int t = 0; t < 9; t++)
            #pragma unroll
            for (int j = 0; j < 4; j++)
                wq[t][j] = wp[(t * IW + 4 * q + j) * CO + co];   // coalesced across co

        #pragma unroll
        for (int iy = 0; iy < 4; iy++) {
            #pragma unroll
            for (int xx = 0; xx < NX + 2; xx++) {
                const uint4 av = *reinterpret_cast<const uint4*>(&sm[iy][xx][4 * q]);
                #pragma unroll
                for (int rr = 0; rr < 2; rr++) {
                    int ky = iy - rr;
                    if (ky < 0 || ky > 2) continue;            // compile-time
                    #pragma unroll
                    for (int kx = 0; kx < 3; kx++) {
                        int o = xx - kx;
                        if (o < 0 || o >= NX) continue;        // compile-time
                        const int t = ky * 3 + kx;
                        uint32_t x1 = av.x ^ wq[t][0];
                        uint32_t x2 = av.y ^ wq[t][1];
                        uint32_t x3 = av.z ^ wq[t][2];
                        uint32_t x4 = av.w ^ wq[t][3];
                        if (t < 3) {                            // direct popc path (1/3 of work)
                            dirm[rr][o] += __popc(x1) + __popc(x2) + __popc(x3) + __popc(x4);
                        } else {                                // CSA path (LOP3-heavy)
                            csa4(ones[rr][o], twos[rr][o], cnt4[rr][o], x1, x2, x3, x4);
                        }
                    }
                }
            }
        }
    }

    // resolve CSA counters + exact SAME-padding corrections
    int pw[9];
    #pragma unroll
    for (int t = 0; t < 9; t++) pw[t] = pwt[t * CO + co];
    float sc = scale[co], tc = bias[co];
    int lane = co & 31, wrp = co >> 5;

    int sums[2][NX];
    #pragma unroll
    for (int rr = 0; rr < 2; rr++) {
        int r = r0 + rr;
        bool top = (r == 0), bot = (r == HW - 1);
        #pragma unroll
        for (int o = 0; o < NX; o++) {
            int mm = dirm[rr][o] + 4 * cnt4[rr][o]
                   + 2 * __popc(twos[rr][o]) + __popc(ones[rr][o]);
            int gx = xb + o;
            bool left = (gx == 0), right = (gx == HW - 1);
            int corr = 0;
            if (top)  corr += pw[0] + pw[1] + pw[2];
            if (bot)  corr += pw[6] + pw[7] + pw[8];
            if (left) {
                corr += pw[0] + pw[3] + pw[6];
                if (top) corr -= pw[0];
                if (bot) corr -= pw[6];
            }
            if (right) {
                corr += pw[2] + pw[5] + pw[8];
                if (top) corr -= pw[2];
                if (bot) corr -= pw[8];
            }
            int nrow = 3 - (top ? 1 : 0) - (bot ? 1 : 0);
            int ncol = 3 - (left ? 1 : 0) - (right ? 1 : 0);
            sums[rr][o] = nrow * ncol * (32 * IW) - 2 * (mm - corr);
        }
    }

    if (POOL) {
        const int HWo = HW / 2;
        #pragma unroll
        for (int xo2 = 0; xo2 < NX / 2; xo2++) {
            int p = max(max(sums[0][2 * xo2], sums[0][2 * xo2 + 1]),
                        max(sums[1][2 * xo2], sums[1][2 * xo2 + 1]));
            p = max(p, 0);                                     // relu then pool == pool then clamp
            float v = __fadd_rn(__fmul_rn((float)p, sc), tc);  // bn: separate roundings
            int xo = xb / 2 + xo2;
            if (FOUT) {
                outf[((n * HWo + yb) * HWo + xo) * CO + co] = v;
            } else {
                unsigned m = __ballot_sync(0xffffffffu, v > 0.f);
                if (lane == 0)
                    outb[((n * HWo + yb) * HWo + xo) * (CO / 32) + wrp] = m;
            }
        }
    } else {
        #pragma unroll
        for (int rr = 0; rr < 2; rr++) {
            #pragma unroll
            for (int o = 0; o < NX; o++) {
                int s = max(sums[rr][o], 0);
                float v = __fadd_rn(__fmul_rn((float)s, sc), tc);
                unsigned m = __ballot_sync(0xffffffffu, v > 0.f);
                if (lane == 0)
                    outb[((n * HW + r0 + rr) * HW + (xb + o)) * (CO / 32) + wrp] = m;
            }
        }
    }
}

// ---------------- dense (bhwc,cd) + bias + softmax ----------------
__global__ void dense_softmax_kernel(const float* __restrict__ dw, const float* __restrict__ db,
                                     float* __restrict__ out) {
    __shared__ float sw[512 * 10];
    __shared__ float sb[10];
    for (int i = threadIdx.x; i < 512 * 10; i += blockDim.x) sw[i] = dw[i];
    if (threadIdx.x < 10) sb[threadIdx.x] = db[threadIdx.x];
    __syncthreads();

    int warp = threadIdx.x >> 5, lane = threadIdx.x & 31;
    int row = blockIdx.x * (blockDim.x >> 5) + warp;
    if (row >= 2048) return;

    float acc[10];
    #pragma unroll
    for (int d = 0; d < 10; d++) acc[d] = 0.f;
    const float* h = g_h6 + row * 512;
    for (int c = lane; c < 512; c += 32) {
        float hv = h[c];
        #pragma unroll
        for (int d = 0; d < 10; d++) acc[d] += hv * sw[c * 10 + d];
    }
    #pragma unroll
    for (int d = 0; d < 10; d++) {
        float v = acc[d];
        #pragma unroll
        for (int o = 16; o; o >>= 1) v += __shfl_xor_sync(0xffffffffu, v, o);
        acc[d] = v;
    }
    if (lane == 0) {
        float mx = -1e30f;
        #pragma unroll
        for (int d = 0; d < 10; d++) { acc[d] += sb[d]; mx = fmaxf(mx, acc[d]); }
        float se = 0.f;
        #pragma unroll
        for (int d = 0; d < 10; d++) { acc[d] = expf(acc[d] - mx); se += acc[d]; }
        float inv = 1.f / se;
        #pragma unroll
        for (int d = 0; d < 10; d++) out[row * 10 + d] = acc[d] * inv;
    }
}

// ---------------- launch ----------------
extern "C" void kernel_launch(void* const* d_in, const int* in_sizes, int n_in,
                              void* d_out, int out_size) {
    const float *x = nullptr, *w1 = nullptr, *b1 = nullptr;
    const float *w2 = nullptr, *w3 = nullptr, *w4 = nullptr, *w5 = nullptr, *w6 = nullptr;
    const float *bns[7] = {0}, *bnb[7] = {0};
    const float *dw = nullptr, *db = nullptr;
    int c128 = 0, c256 = 0, c512 = 0;
    for (int i = 0; i < n_in; i++) {
        const float* p = (const float*)d_in[i];
        switch (in_sizes[i]) {
            case 393216:  x  = p; break;
            case 3456:    w1 = p; break;
            case 147456:  w2 = p; break;
            case 294912:  w3 = p; break;
            case 589824:  w4 = p; break;
            case 1179648: w5 = p; break;
            case 2359296: w6 = p; break;
            case 5120:    dw = p; break;
            case 10:      db = p; break;
            case 128:
                if      (c128 == 0) b1     = p;
                else if (c128 == 1) bns[1] = p;
                else if (c128 == 2) bnb[1] = p;
                else if (c128 == 3) bns[2] = p;
                else                bnb[2] = p;
                c128++; break;
            case 256:
                if      (c256 == 0) bns[3] = p;
                else if (c256 == 1) bnb[3] = p;
                else if (c256 == 2) bns[4] = p;
                else                bnb[4] = p;
                c256++; break;
            case 512:
                if      (c512 == 0) bns[5] = p;
                else if (c512 == 1) bnb[5] = p;
                else if (c512 == 2) bns[6] = p;
                else                bnb[6] = p;
                c512++; break;
            default: break;
        }
    }

    void *p_h1, *p_h2, *p_h3, *p_h4, *p_h5, *p_h6;
    void *p_w2, *p_w3, *p_w4, *p_w5, *p_w6;
    void *p_pw2, *p_pw3, *p_pw4, *p_pw5, *p_pw6;
    cudaGetSymbolAddress(&p_h1, g_h1p);
    cudaGetSymbolAddress(&p_h2, g_h2p);
    cudaGetSymbolAddress(&p_h3, g_h3p);
    cudaGetSymbolAddress(&p_h4, g_h4p);
    cudaGetSymbolAddress(&p_h5, g_h5p);
    cudaGetSymbolAddress(&p_h6, g_h6);
    cudaGetSymbolAddress(&p_w2, g_w2p);
    cudaGetSymbolAddress(&p_w3, g_w3p);
    cudaGetSymbolAddress(&p_w4, g_w4p);
    cudaGetSymbolAddress(&p_w5, g_w5p);
    cudaGetSymbolAddress(&p_w6, g_w6p);
    cudaGetSymbolAddress(&p_pw2, g_pw2);
    cudaGetSymbolAddress(&p_pw3, g_pw3);
    cudaGetSymbolAddress(&p_pw4, g_pw4);
    cudaGetSymbolAddress(&p_pw5, g_pw5);
    cudaGetSymbolAddress(&p_pw6, g_pw6);

    // prep: packs + pw tables + conv1
    prep_kernel<<<2665, 256>>>(x, w1, b1, bns[1], bnb[1], w2, w3, w4, w5, w6);

    // binary conv stack (CSA counting)
    bconv6_kernel<4, 128, 32, 8, true,  false><<<dim3(16 * 4, 128, 1), 128>>>(
        (const uint32_t*)p_h1, (const uint32_t*)p_w2, (const int*)p_pw2,
        bns[2], bnb[2], (uint32_t*)p_h2, nullptr);
    bconv6_kernel<4, 256, 16, 8, false, false><<<dim3(8 * 2, 128, 2), 128>>>(
        (const uint32_t*)p_h2, (const uint32_t*)p_w3, (const int*)p_pw3,
        bns[3], bnb[3], (uint32_t*)p_h3, nullptr);
    bconv6_kernel<8, 256, 16, 8, true,  false><<<dim3(8 * 2, 128, 2), 128>>>(
        (const uint32_t*)p_h3, (const uint32_t*)p_w4, (const int*)p_pw4,
        bns[4], bnb[4], (uint32_t*)p_h4, nullptr);
    bconv6_kernel<8, 512, 8, 8,  false, false><<<dim3(4 * 1, 128, 4), 128>>>(
        (const uint32_t*)p_h4, (const uint32_t*)p_w5, (const int*)p_pw5,
        bns[5], bnb[5], (uint32_t*)p_h5, nullptr);
    bconv6_kernel<16, 512, 8, 8, true,  true ><<<dim3(4 * 1, 128, 4), 128>>>(
        (const uint32_t*)p_h5, (const uint32_t*)p_w6, (const int*)p_pw6,
        bns[6], bnb[6], nullptr, (float*)p_h6);

    // dense + softmax
    dense_softmax_kernel<<<256, 256>>>(dw, db, (float*)d_out);
}

// round 17
// speedup vs baseline: 2.3459x; 1.1032x over previous
#include <cuda_runtime.h>
#include <cstdint>
#include <math.h>

// ---------------- device scratch (no allocation allowed) ----------------
__device__ uint32_t g_h1p[128*32*32*4];
__device__ uint32_t g_h2p[128*16*16*4];
__device__ uint32_t g_h3p[128*16*16*8];
__device__ uint32_t g_h4p[128*8*8*8];
__device__ uint32_t g_h5p[128*8*8*16];
__device__ float    g_h6 [128*4*4*512];
__device__ uint32_t g_w2p[9*4*128];
__device__ uint32_t g_w3p[9*4*256];
__device__ uint32_t g_w4p[9*8*256];
__device__ uint32_t g_w5p[9*8*512];
__device__ uint32_t g_w6p[9*16*512];
__device__ int      g_pw2[9*128];           // per-tap weight popcounts (edge corrections)
__device__ int      g_pw3[9*256];
__device__ int      g_pw4[9*256];
__device__ int      g_pw5[9*512];
__device__ int      g_pw6[9*512];

// ---------------- single-LOP3 parity / majority (guaranteed one SASS op) ----------------
template<int IMM>
__device__ __forceinline__ uint32_t lop3i(uint32_t a, uint32_t b, uint32_t c) {
    uint32_t r;
    asm("lop3.b32 %0, %1, %2, %3, %4;" : "=r"(r) : "r"(a), "r"(b), "r"(c), "n"(IMM));
    return r;
}
// 2-wide carry-save absorb: state `ones` + counter. Per pair of bit-vectors:
// 1 parity LOP3 + 1 majority LOP3 + 1 POPC + 1 IADD.  mm = 2*cnt2 + popc(ones).
__device__ __forceinline__ void csa2(uint32_t& ones, int& cnt2, uint32_t x1, uint32_t x2) {
    uint32_t s = lop3i<0x96>(ones, x1, x2);   // parity
    uint32_t c = lop3i<0xE8>(ones, x1, x2);   // majority (carries, worth 2 each)
    ones = s;
    cnt2 += __popc(c);
}

// ---------------- weight bit-packing (device helper) ----------------
__device__ __forceinline__ void pack_dev(const float* __restrict__ w, uint32_t* __restrict__ wp,
                                         int CI, int CO, int idx) {
    int IW = CI / 32;
    int total = 9 * IW * CO;
    if (idx >= total) return;
    int co   = idx % CO;
    int word = (idx / CO) % IW;
    int tap  = idx / (CO * IW);
    uint32_t bits = 0;
    #pragma unroll 8
    for (int b = 0; b < 32; b++) {
        float v = w[(tap * CI + word * 32 + b) * CO + co];
        bits |= (v > 0.f ? 1u : 0u) << b;
    }
    wp[(tap * IW + word) * CO + co] = bits;
}

// ---------------- per-tap weight popcount tables ----------------
__device__ __forceinline__ void pw_dev(const float* __restrict__ w, int* __restrict__ pwt,
                                       int CI, int CO, int idx) {
    if (idx >= 9 * CO) return;
    int co = idx % CO, t = idx / CO;
    int cnt = 0;
    for (int ci = 0; ci < CI; ci++)
        cnt += (w[(t * CI + ci) * CO + co] > 0.f) ? 1 : 0;
    pwt[t * CO + co] = cnt;
}

// ---------------- conv1 (device helper) ----------------
__device__ __forceinline__ void conv1_dev(const float* __restrict__ x, const float* __restrict__ w1,
                                          const float* __restrict__ b1, const float* __restrict__ s1,
                                          const float* __restrict__ t1, int bid, int tid) {
    __shared__ float sx[4][34][3];
    int n = bid >> 4, yb = bid & 15;
    int half = tid >> 7, c = tid & 127;
    int y = 2 * yb + half;

    for (int i = tid; i < 4 * 34 * 3; i += 256) {
        int ci = i % 3;
        int xx = (i / 3) % 34;
        int r  = i / (3 * 34);
        int yy = 2 * yb - 1 + r;
        int xs = xx - 1;
        float v = 0.f;
        if (yy >= 0 && yy < 32 && xs >= 0 && xs < 32)
            v = x[((n * 32 + yy) * 32 + xs) * 3 + ci];
        sx[r][xx][ci] = v;
    }
    __syncthreads();

    float wr[27];
    #pragma unroll
    for (int k = 0; k < 27; k++) wr[k] = w1[k * 128 + c];
    float bb = b1[c], sc = s1[c], tc = t1[c];
    int lane = c & 31, wrp = c >> 5;

    for (int xo = 0; xo < 32; xo++) {
        float acc = 0.f;
        #pragma unroll
        for (int ky = 0; ky < 3; ky++)
            #pragma unroll
            for (int kx = 0; kx < 3; kx++)
                #pragma unroll
                for (int ci = 0; ci < 3; ci++)
                    acc = fmaf(sx[half + ky][xo + kx][ci], wr[(ky * 3 + kx) * 3 + ci], acc);
        float z = __fadd_rn(acc, bb);
        float r = fmaxf(z, 0.f);
        float v = __fadd_rn(__fmul_rn(r, sc), tc);
        unsigned m = __ballot_sync(0xffffffffu, v > 0.f);
        if (lane == 0) g_h1p[((n * 32 + y) * 32 + xo) * 4 + wrp] = m;
    }
}

// ---------------- fused prep: 5 packs + 5 pw tables + conv1 ----------------
// [0,18) w2  [18,54) w3  [54,126) w4  [126,270) w5  [270,558) w6
// [558,563) pw2 [563,572) pw3 [572,581) pw4 [581,599) pw5 [599,617) pw6 [617,2665) conv1
__global__ void __launch_bounds__(256)
prep_kernel(const float* __restrict__ x,  const float* __restrict__ w1,
            const float* __restrict__ b1, const float* __restrict__ s1, const float* __restrict__ t1,
            const float* __restrict__ w2, const float* __restrict__ w3, const float* __restrict__ w4,
            const float* __restrict__ w5, const float* __restrict__ w6) {
    int bid = blockIdx.x, tid = threadIdx.x;
    if      (bid < 18)  pack_dev(w2, g_w2p, 128, 128, bid * 256 + tid);
    else if (bid < 54)  pack_dev(w3, g_w3p, 128, 256, (bid - 18)  * 256 + tid);
    else if (bid < 126) pack_dev(w4, g_w4p, 256, 256, (bid - 54)  * 256 + tid);
    else if (bid < 270) pack_dev(w5, g_w5p, 256, 512, (bid - 126) * 256 + tid);
    else if (bid < 558) pack_dev(w6, g_w6p, 512, 512, (bid - 270) * 256 + tid);
    else if (bid < 563) pw_dev(w2, g_pw2, 128, 128, (bid - 558) * 256 + tid);
    else if (bid < 572) pw_dev(w3, g_pw3, 128, 256, (bid - 563) * 256 + tid);
    else if (bid < 581) pw_dev(w4, g_pw4, 256, 256, (bid - 572) * 256 + tid);
    else if (bid < 599) pw_dev(w5, g_pw5, 256, 512, (bid - 581) * 256 + tid);
    else if (bid < 617) pw_dev(w6, g_pw6, 512, 512, (bid - 599) * 256 + tid);
    else                conv1_dev(x, w1, b1, s1, t1, bid - 617, tid);
}

// ---------------- binary conv v7: uniform CSA2 counting (ALU/POPC pipes balanced 4:1) ----
// in: packed [N, HW, HW, IW]; wp: [9, IW, CO]; pwt: [9, CO].
// Per word pair per tap-use: 2 XOR + 1 parity + 1 maj (ALU) + 1 POPC + 1 IADD.
// grid = ((HW/2)*(HW/NX), N, CO/128), block 128.
template<int IW, int CO, int HW, int NX, bool POOL, bool FOUT>
__global__ void __launch_bounds__(128)
bconv7_kernel(const uint32_t* __restrict__ in, const uint32_t* __restrict__ wp,
              const int* __restrict__ pwt,
              const float* __restrict__ scale, const float* __restrict__ bias,
              uint32_t* __restrict__ outb, float* __restrict__ outf) {
    const int XB = HW / NX;
    const int QW = IW / 4;
    int bx = blockIdx.x, n = blockIdx.y;
    int co = blockIdx.z * 128 + threadIdx.x;
    int xchunk = bx % XB, yb = bx / XB;
    int r0 = 2 * yb, xb = xchunk * NX;

    __shared__ __align__(16) uint32_t sm[4][NX + 2][IW];
    for (int i = threadIdx.x; i < 4 * (NX + 2) * IW; i += 128) {
        int w  = i % IW;
        int xx = (i / IW) % (NX + 2);
        int rr = i / (IW * (NX + 2));
        int yy = r0 - 1 + rr;
        int xs = xb + xx - 1;
        uint32_t v = 0;
        if (yy >= 0 && yy < HW && xs >= 0 && xs < HW)
            v = in[((n * HW + yy) * HW + xs) * IW + w];
        sm[rr][xx][w] = v;
    }
    __syncthreads();

    uint32_t ones[2][NX];
    int      cnt2[2][NX];
    #pragma unroll
    for (int rr = 0; rr < 2; rr++)
        #pragma unroll
        for (int o = 0; o < NX; o++) { ones[rr][o] = 0u; cnt2[rr][o] = 0; }

    #pragma unroll 1
    for (int q = 0; q < QW; q++) {
        uint32_t wq[9][4];
        #pragma unroll
        for (int t = 0; t < 9; t++)
            #pragma unroll
            for (int j = 0; j < 4; j++)
                wq[t][j] = wp[(t * IW + 4 * q + j) * CO + co];   // coalesced across co

        #pragma unroll
        for (int iy = 0; iy < 4; iy++) {
            #pragma unroll
            for (int xx = 0; xx < NX + 2; xx++) {
                const uint4 av = *reinterpret_cast<const uint4*>(&sm[iy][xx][4 * q]);
                #pragma unroll
                for (int rr = 0; rr < 2; rr++) {
                    int ky = iy - rr;
                    if (ky < 0 || ky > 2) continue;            // compile-time
                    #pragma unroll
                    for (int kx = 0; kx < 3; kx++) {
                        int o = xx - kx;
                        if (o < 0 || o >= NX) continue;        // compile-time
                        const int t = ky * 3 + kx;
                        csa2(ones[rr][o], cnt2[rr][o],
                             av.x ^ wq[t][0], av.y ^ wq[t][1]);
                        csa2(ones[rr][o], cnt2[rr][o],
                             av.z ^ wq[t][2], av.w ^ wq[t][3]);
                    }
                }
            }
        }
    }

    // resolve CSA counters + exact SAME-padding corrections
    int pw[9];
    #pragma unroll
    for (int t = 0; t < 9; t++) pw[t] = pwt[t * CO + co];
    float sc = scale[co], tc = bias[co];
    int lane = co & 31, wrp = co >> 5;

    int sums[2][NX];
    #pragma unroll
    for (int rr = 0; rr < 2; rr++) {
        int r = r0 + rr;
        bool top = (r == 0), bot = (r == HW - 1);
        #pragma unroll
        for (int o = 0; o < NX; o++) {
            int mm = 2 * cnt2[rr][o] + __popc(ones[rr][o]);
            int gx = xb + o;
            bool left = (gx == 0), right = (gx == HW - 1);
            int corr = 0;
            if (top)  corr += pw[0] + pw[1] + pw[2];
            if (bot)  corr += pw[6] + pw[7] + pw[8];
            if (left) {
                corr += pw[0] + pw[3] + pw[6];
                if (top) corr -= pw[0];
                if (bot) corr -= pw[6];
            }
            if (right) {
                corr += pw[2] + pw[5] + pw[8];
                if (top) corr -= pw[2];
                if (bot) corr -= pw[8];
            }
            int nrow = 3 - (top ? 1 : 0) - (bot ? 1 : 0);
            int ncol = 3 - (left ? 1 : 0) - (right ? 1 : 0);
            sums[rr][o] = nrow * ncol * (32 * IW) - 2 * (mm - corr);
        }
    }

    if (POOL) {
        const int HWo = HW / 2;
        #pragma unroll
        for (int xo2 = 0; xo2 < NX / 2; xo2++) {
            int p = max(max(sums[0][2 * xo2], sums[0][2 * xo2 + 1]),
                        max(sums[1][2 * xo2], sums[1][2 * xo2 + 1]));
            p = max(p, 0);                                     // relu then pool == pool then clamp
            float v = __fadd_rn(__fmul_rn((float)p, sc), tc);  // bn: separate roundings
            int xo = xb / 2 + xo2;
            if (FOUT) {
                outf[((n * HWo + yb) * HWo + xo) * CO + co] = v;
            } else {
                unsigned m = __ballot_sync(0xffffffffu, v > 0.f);
                if (lane == 0)
                    outb[((n * HWo + yb) * HWo + xo) * (CO / 32) + wrp] = m;
            }
        }
    } else {
        #pragma unroll
        for (int rr = 0; rr < 2; rr++) {
            #pragma unroll
            for (int o = 0; o < NX; o++) {
                int s = max(sums[rr][o], 0);
                float v = __fadd_rn(__fmul_rn((float)s, sc), tc);
                unsigned m = __ballot_sync(0xffffffffu, v > 0.f);
                if (lane == 0)
                    outb[((n * HW + r0 + rr) * HW + (xb + o)) * (CO / 32) + wrp] = m;
            }
        }
    }
}

// ---------------- dense (bhwc,cd) + bias + softmax ----------------
__global__ void dense_softmax_kernel(const float* __restrict__ dw, const float* __restrict__ db,
                                     float* __restrict__ out) {
    __shared__ float sw[512 * 10];
    __shared__ float sb[10];
    for (int i = threadIdx.x; i < 512 * 10; i += blockDim.x) sw[i] = dw[i];
    if (threadIdx.x < 10) sb[threadIdx.x] = db[threadIdx.x];
    __syncthreads();

    int warp = threadIdx.x >> 5, lane = threadIdx.x & 31;
    int row = blockIdx.x * (blockDim.x >> 5) + warp;
    if (row >= 2048) return;

    float acc[10];
    #pragma unroll
    for (int d = 0; d < 10; d++) acc[d] = 0.f;
    const float* h = g_h6 + row * 512;
    for (int c = lane; c < 512; c += 32) {
        float hv = h[c];
        #pragma unroll
        for (int d = 0; d < 10; d++) acc[d] += hv * sw[c * 10 + d];
    }
    #pragma unroll
    for (int d = 0; d < 10; d++) {
        float v = acc[d];
        #pragma unroll
        for (int o = 16; o; o >>= 1) v += __shfl_xor_sync(0xffffffffu, v, o);
        acc[d] = v;
    }
    if (lane == 0) {
        float mx = -1e30f;
        #pragma unroll
        for (int d = 0; d < 10; d++) { acc[d] += sb[d]; mx = fmaxf(mx, acc[d]); }
        float se = 0.f;
        #pragma unroll
        for (int d = 0; d < 10; d++) { acc[d] = expf(acc[d] - mx); se += acc[d]; }
        float inv = 1.f / se;
        #pragma unroll
        for (int d = 0; d < 10; d++) out[row * 10 + d] = acc[d] * inv;
    }
}

// ---------------- launch ----------------
extern "C" void kernel_launch(void* const* d_in, const int* in_sizes, int n_in,
                              void* d_out, int out_size) {
    const float *x = nullptr, *w1 = nullptr, *b1 = nullptr;
    const float *w2 = nullptr, *w3 = nullptr, *w4 = nullptr, *w5 = nullptr, *w6 = nullptr;
    const float *bns[7] = {0}, *bnb[7] = {0};
    const float *dw = nullptr, *db = nullptr;
    int c128 = 0, c256 = 0, c512 = 0;
    for (int i = 0; i < n_in; i++) {
        const float* p = (const float*)d_in[i];
        switch (in_sizes[i]) {
            case 393216:  x  = p; break;
            case 3456:    w1 = p; break;
            case 147456:  w2 = p; break;
            case 294912:  w3 = p; break;
            case 589824:  w4 = p; break;
            case 1179648: w5 = p; break;
            case 2359296: w6 = p; break;
            case 5120:    dw = p; break;
            case 10:      db = p; break;
            case 128:
                if      (c128 == 0) b1     = p;
                else if (c128 == 1) bns[1] = p;
                else if (c128 == 2) bnb[1] = p;
                else if (c128 == 3) bns[2] = p;
                else                bnb[2] = p;
                c128++; break;
            case 256:
                if      (c256 == 0) bns[3] = p;
                else if (c256 == 1) bnb[3] = p;
                else if (c256 == 2) bns[4] = p;
                else                bnb[4] = p;
                c256++; break;
            case 512:
                if      (c512 == 0) bns[5] = p;
                else if (c512 == 1) bnb[5] = p;
                else if (c512 == 2) bns[6] = p;
                else                bnb[6] = p;
                c512++; break;
            default: break;
        }
    }

    void *p_h1, *p_h2, *p_h3, *p_h4, *p_h5, *p_h6;
    void *p_w2, *p_w3, *p_w4, *p_w5, *p_w6;
    void *p_pw2, *p_pw3, *p_pw4, *p_pw5, *p_pw6;
    cudaGetSymbolAddress(&p_h1, g_h1p);
    cudaGetSymbolAddress(&p_h2, g_h2p);
    cudaGetSymbolAddress(&p_h3, g_h3p);
    cudaGetSymbolAddress(&p_h4, g_h4p);
    cudaGetSymbolAddress(&p_h5, g_h5p);
    cudaGetSymbolAddress(&p_h6, g_h6);
    cudaGetSymbolAddress(&p_w2, g_w2p);
    cudaGetSymbolAddress(&p_w3, g_w3p);
    cudaGetSymbolAddress(&p_w4, g_w4p);
    cudaGetSymbolAddress(&p_w5, g_w5p);
    cudaGetSymbolAddress(&p_w6, g_w6p);
    cudaGetSymbolAddress(&p_pw2, g_pw2);
    cudaGetSymbolAddress(&p_pw3, g_pw3);
    cudaGetSymbolAddress(&p_pw4, g_pw4);
    cudaGetSymbolAddress(&p_pw5, g_pw5);
    cudaGetSymbolAddress(&p_pw6, g_pw6);

    // prep: packs + pw tables + conv1
    prep_kernel<<<2665, 256>>>(x, w1, b1, bns[1], bnb[1], w2, w3, w4, w5, w6);

    // binary conv stack (CSA2 counting)
    bconv7_kernel<4, 128, 32, 8, true,  false><<<dim3(16 * 4, 128, 1), 128>>>(
        (const uint32_t*)p_h1, (const uint32_t*)p_w2, (const int*)p_pw2,
        bns[2], bnb[2], (uint32_t*)p_h2, nullptr);
    bconv7_kernel<4, 256, 16, 8, false, false><<<dim3(8 * 2, 128, 2), 128>>>(
        (const uint32_t*)p_h2, (const uint32_t*)p_w3, (const int*)p_pw3,
        bns[3], bnb[3], (uint32_t*)p_h3, nullptr);
    bconv7_kernel<8, 256, 16, 8, true,  false><<<dim3(8 * 2, 128, 2), 128>>>(
        (const uint32_t*)p_h3, (const uint32_t*)p_w4, (const int*)p_pw4,
        bns[4], bnb[4], (uint32_t*)p_h4, nullptr);
    bconv7_kernel<8, 512, 8, 8,  false, false><<<dim3(4 * 1, 128, 4), 128>>>(
        (const uint32_t*)p_h4, (const uint32_t*)p_w5, (const int*)p_pw5,
        bns[5], bnb[5], (uint32_t*)p_h5, nullptr);
    bconv7_kernel<16, 512, 8, 8, true,  true ><<<dim3(4 * 1, 128, 4), 128>>>(
        (const uint32_t*)p_h5, (const uint32_t*)p_w6, (const int*)p_pw6,
        bns[6], bnb[6], nullptr, (float*)p_h6);

    // dense + softmax
    dense_softmax_kernel<<<256, 256>>>(dw, db, (float*)d_out);
}